// round 1
// baseline (speedup 1.0000x reference)
#include <cuda_runtime.h>

// CAN co-action unit: per-sample 2-layer MLP, D=16, N=50, B=16384.
// x (B,N,D); params per sample: W0(16x16), b0(16), W1(16x16), b1(16) = 544 floats.
// out[b,n,e] = relu( relu(x W0 + b0) W1 + b1 )
//
// Memory-bound: ~140MB total traffic, ~0.84 GFLOP. One CTA per sample,
// everything staged through SMEM, fully coalesced float4 global accesses.

#define D 16
#define N 50
#define PARAMS 544          // 2*(256+16)
#define XELEMS (N * D)      // 800
#define THREADS 256

__global__ __launch_bounds__(THREADS) void can_kernel(
    const float* __restrict__ user_emb,
    const float* __restrict__ item_emb,
    float* __restrict__ out)
{
    const int b = blockIdx.x;
    __shared__ float sp[PARAMS];   // W0 | b0 | W1 | b1
    __shared__ float xa[XELEMS];   // input tile
    __shared__ float xb[XELEMS];   // layer-1 activations

    // Coalesced float4 staging: 136 vec4 for params, 200 vec4 for x.
    const float4* ip = (const float4*)(item_emb + (size_t)b * PARAMS);
    for (int i = threadIdx.x; i < PARAMS / 4; i += THREADS)
        ((float4*)sp)[i] = ip[i];
    const float4* up = (const float4*)(user_emb + (size_t)b * XELEMS);
    for (int i = threadIdx.x; i < XELEMS / 4; i += THREADS)
        ((float4*)xa)[i] = up[i];
    __syncthreads();

    // Layer 1: xb[n,e] = relu( sum_d xa[n,d]*W0[d,e] + b0[e] )
    // W0 = sp[0..255], b0 = sp[256..271]
    for (int idx = threadIdx.x; idx < XELEMS; idx += THREADS) {
        const int n = idx >> 4;
        const int e = idx & 15;
        const float* xr = xa + n * D;
        float acc = sp[256 + e];
        #pragma unroll
        for (int d = 0; d < D; d++)
            acc = fmaf(xr[d], sp[d * D + e], acc);
        xb[idx] = fmaxf(acc, 0.0f);
    }
    __syncthreads();

    // Layer 2: out[n,e] = relu( sum_d xb[n,d]*W1[d,e] + b1[e] ), streamed to GMEM.
    // W1 = sp[272..527], b1 = sp[528..543]
    float* ob = out + (size_t)b * XELEMS;
    for (int idx = threadIdx.x; idx < XELEMS; idx += THREADS) {
        const int n = idx >> 4;
        const int e = idx & 15;
        const float* xr = xb + n * D;
        float acc = sp[528 + e];
        #pragma unroll
        for (int d = 0; d < D; d++)
            acc = fmaf(xr[d], sp[272 + d * D + e], acc);
        ob[idx] = fmaxf(acc, 0.0f);
    }
}

extern "C" void kernel_launch(void* const* d_in, const int* in_sizes, int n_in,
                              void* d_out, int out_size) {
    const float* user_emb = (const float*)d_in[0];
    const float* item_emb = (const float*)d_in[1];
    float* out = (float*)d_out;
    const int B = in_sizes[1] / PARAMS;   // 16384
    can_kernel<<<B, THREADS>>>(user_emb, item_emb, out);
}

// round 2
// speedup vs baseline: 1.2563x; 1.2563x over previous
#include <cuda_runtime.h>

// CAN co-action unit: per-sample 2-layer MLP, D=16, N=50, B=16384.
// Row-per-thread: x row lives in registers across both layers; only the
// per-sample weights go through SMEM (LDS.128, broadcast within a sample,
// bank-disjoint across the <=2 samples a warp spans via 552-float pad).

#define D 16
#define N 50
#define PARAMS 544            // 2*(256+16)
#define PSTRIDE 552           // padded stride (552 % 32 == 8 -> bank-shifted)
#define SAMPLES_PER_CTA 8
#define ROWS_PER_CTA (SAMPLES_PER_CTA * N)   // 400
#define THREADS 416           // 13 warps; threads [400,416) idle

__global__ __launch_bounds__(THREADS) void can_kernel(
    const float* __restrict__ user_emb,
    const float* __restrict__ item_emb,
    float* __restrict__ out)
{
    __shared__ float sp[SAMPLES_PER_CTA * PSTRIDE];  // W0|b0|W1|b1 per sample

    const int t = threadIdx.x;

    // ---- Stage params for 8 samples, coalesced float4, into padded layout.
    // 136 float4 per sample; dst float4 stride 138 (= 552/4).
    {
        const float4* src = (const float4*)(item_emb
                            + (size_t)blockIdx.x * SAMPLES_PER_CTA * PARAMS);
        #pragma unroll
        for (int k = 0; k < 3; k++) {
            int i = t + k * THREADS;                 // 0..1247 covers 1088
            if (i < SAMPLES_PER_CTA * (PARAMS / 4)) {
                int si = i / (PARAMS / 4);
                int wi = i - si * (PARAMS / 4);
                ((float4*)sp)[si * (PSTRIDE / 4) + wi] = src[i];
            }
        }
    }

    // ---- Load this thread's x row straight into registers (4x LDG.128).
    float x[D];
    const size_t grow = (size_t)blockIdx.x * ROWS_PER_CTA + t;  // global row
    if (t < ROWS_PER_CTA) {
        const float4* xr = (const float4*)(user_emb + grow * D);
        #pragma unroll
        for (int j = 0; j < 4; j++) {
            float4 v = xr[j];
            x[j * 4 + 0] = v.x; x[j * 4 + 1] = v.y;
            x[j * 4 + 2] = v.z; x[j * 4 + 3] = v.w;
        }
    }
    __syncthreads();

    if (t >= ROWS_PER_CTA) return;

    const int b_local = t / N;
    const float* p = sp + b_local * PSTRIDE;

    float acc[D];

    // ---- Layer 1: acc[e] = relu( sum_d x[d]*W0[d][e] + b0[e] )
    {
        const float4* bias = (const float4*)(p + 256);
        #pragma unroll
        for (int j = 0; j < 4; j++) {
            float4 v = bias[j];
            acc[j * 4 + 0] = v.x; acc[j * 4 + 1] = v.y;
            acc[j * 4 + 2] = v.z; acc[j * 4 + 3] = v.w;
        }
        #pragma unroll
        for (int d = 0; d < D; d++) {
            const float4* wr = (const float4*)(p + d * D);  // W0 row d
            const float xd = x[d];
            #pragma unroll
            for (int j = 0; j < 4; j++) {
                float4 w = wr[j];
                acc[j * 4 + 0] = fmaf(xd, w.x, acc[j * 4 + 0]);
                acc[j * 4 + 1] = fmaf(xd, w.y, acc[j * 4 + 1]);
                acc[j * 4 + 2] = fmaf(xd, w.z, acc[j * 4 + 2]);
                acc[j * 4 + 3] = fmaf(xd, w.w, acc[j * 4 + 3]);
            }
        }
        #pragma unroll
        for (int e = 0; e < D; e++) x[e] = fmaxf(acc[e], 0.0f);
    }

    // ---- Layer 2: acc[e] = relu( sum_d x[d]*W1[d][e] + b1[e] )
    {
        const float4* bias = (const float4*)(p + 528);
        #pragma unroll
        for (int j = 0; j < 4; j++) {
            float4 v = bias[j];
            acc[j * 4 + 0] = v.x; acc[j * 4 + 1] = v.y;
            acc[j * 4 + 2] = v.z; acc[j * 4 + 3] = v.w;
        }
        #pragma unroll
        for (int d = 0; d < D; d++) {
            const float4* wr = (const float4*)(p + 272 + d * D);  // W1 row d
            const float xd = x[d];
            #pragma unroll
            for (int j = 0; j < 4; j++) {
                float4 w = wr[j];
                acc[j * 4 + 0] = fmaf(xd, w.x, acc[j * 4 + 0]);
                acc[j * 4 + 1] = fmaf(xd, w.y, acc[j * 4 + 1]);
                acc[j * 4 + 2] = fmaf(xd, w.z, acc[j * 4 + 2]);
                acc[j * 4 + 3] = fmaf(xd, w.w, acc[j * 4 + 3]);
            }
        }
    }

    // ---- Store (4x STG.128)
    float4* orow = (float4*)(out + grow * D);
    #pragma unroll
    for (int j = 0; j < 4; j++) {
        float4 v;
        v.x = fmaxf(acc[j * 4 + 0], 0.0f);
        v.y = fmaxf(acc[j * 4 + 1], 0.0f);
        v.z = fmaxf(acc[j * 4 + 2], 0.0f);
        v.w = fmaxf(acc[j * 4 + 3], 0.0f);
        orow[j] = v;
    }
}

extern "C" void kernel_launch(void* const* d_in, const int* in_sizes, int n_in,
                              void* d_out, int out_size) {
    const float* user_emb = (const float*)d_in[0];
    const float* item_emb = (const float*)d_in[1];
    float* out = (float*)d_out;
    const int B = in_sizes[1] / PARAMS;        // 16384
    const int blocks = B / SAMPLES_PER_CTA;    // 2048
    can_kernel<<<blocks, THREADS>>>(user_emb, item_emb, out);
}

// round 3
// speedup vs baseline: 1.3087x; 1.0417x over previous
#include <cuda_runtime.h>

// CAN co-action unit: per-sample 2-layer MLP, D=16, N=50, B=16384.
// Two rows per thread (same sample): each W row is loaded from SMEM once
// (4x LDS.128) and applied to both rows, halving the LDS instruction count
// that bound the previous version. Activations live in registers end-to-end.

#define D 16
#define N 50
#define PARAMS 544            // 2*(256+16)
#define PSTRIDE 552           // padded stride (552 % 32 == 8 -> bank-shifted)
#define SAMPLES_PER_CTA 8
#define ROWS_PER_CTA (SAMPLES_PER_CTA * N)       // 400
#define ACTIVE (SAMPLES_PER_CTA * (N / 2))       // 200 threads do 2 rows each
#define THREADS 224                              // 7 warps

__global__ __launch_bounds__(THREADS, 3) void can_kernel(
    const float* __restrict__ user_emb,
    const float* __restrict__ item_emb,
    float* __restrict__ out)
{
    __shared__ float sp[SAMPLES_PER_CTA * PSTRIDE];  // W0|b0|W1|b1 per sample

    const int t = threadIdx.x;

    // ---- Stage params for 8 samples (136 float4 each) into padded layout.
    {
        const float4* src = (const float4*)(item_emb
                            + (size_t)blockIdx.x * SAMPLES_PER_CTA * PARAMS);
        #pragma unroll
        for (int k = 0; k < 5; k++) {
            int i = t + k * THREADS;                 // covers 1088
            if (i < SAMPLES_PER_CTA * (PARAMS / 4)) {
                int si = i / (PARAMS / 4);
                int wi = i - si * (PARAMS / 4);
                ((float4*)sp)[si * (PSTRIDE / 4) + wi] = src[i];
            }
        }
    }

    // ---- This thread's two rows (same sample): rows j and j+25 of sample s.
    const int s = t / (N / 2);        // 0..7
    const int j = t - s * (N / 2);    // 0..24
    const bool active = (t < ACTIVE);

    const size_t base_row = (size_t)blockIdx.x * ROWS_PER_CTA + s * N + j;
    float x0[D], x1[D];
    if (active) {
        const float4* r0 = (const float4*)(user_emb + base_row * D);
        const float4* r1 = (const float4*)(user_emb + (base_row + N / 2) * D);
        #pragma unroll
        for (int q = 0; q < 4; q++) {
            float4 a = r0[q], b = r1[q];
            x0[q*4+0]=a.x; x0[q*4+1]=a.y; x0[q*4+2]=a.z; x0[q*4+3]=a.w;
            x1[q*4+0]=b.x; x1[q*4+1]=b.y; x1[q*4+2]=b.z; x1[q*4+3]=b.w;
        }
    }
    __syncthreads();

    if (!active) return;

    const float* p = sp + s * PSTRIDE;
    float a0[D], a1[D];

    // ---- Layer 1: a = relu(x W0 + b0);  W0 = p[0..255], b0 = p[256..271]
    {
        const float4* bias = (const float4*)(p + 256);
        #pragma unroll
        for (int q = 0; q < 4; q++) {
            float4 v = bias[q];
            a0[q*4+0]=v.x; a0[q*4+1]=v.y; a0[q*4+2]=v.z; a0[q*4+3]=v.w;
            a1[q*4+0]=v.x; a1[q*4+1]=v.y; a1[q*4+2]=v.z; a1[q*4+3]=v.w;
        }
        #pragma unroll
        for (int d = 0; d < D; d++) {
            const float4* wr = (const float4*)(p + d * D);
            const float u0 = x0[d], u1 = x1[d];
            #pragma unroll
            for (int q = 0; q < 4; q++) {
                float4 w = wr[q];
                a0[q*4+0]=fmaf(u0,w.x,a0[q*4+0]); a1[q*4+0]=fmaf(u1,w.x,a1[q*4+0]);
                a0[q*4+1]=fmaf(u0,w.y,a0[q*4+1]); a1[q*4+1]=fmaf(u1,w.y,a1[q*4+1]);
                a0[q*4+2]=fmaf(u0,w.z,a0[q*4+2]); a1[q*4+2]=fmaf(u1,w.z,a1[q*4+2]);
                a0[q*4+3]=fmaf(u0,w.w,a0[q*4+3]); a1[q*4+3]=fmaf(u1,w.w,a1[q*4+3]);
            }
        }
        #pragma unroll
        for (int e = 0; e < D; e++) {
            x0[e] = fmaxf(a0[e], 0.0f);
            x1[e] = fmaxf(a1[e], 0.0f);
        }
    }

    // ---- Layer 2: a = x W1 + b1;  W1 = p[272..527], b1 = p[528..543]
    {
        const float4* bias = (const float4*)(p + 528);
        #pragma unroll
        for (int q = 0; q < 4; q++) {
            float4 v = bias[q];
            a0[q*4+0]=v.x; a0[q*4+1]=v.y; a0[q*4+2]=v.z; a0[q*4+3]=v.w;
            a1[q*4+0]=v.x; a1[q*4+1]=v.y; a1[q*4+2]=v.z; a1[q*4+3]=v.w;
        }
        #pragma unroll
        for (int d = 0; d < D; d++) {
            const float4* wr = (const float4*)(p + 272 + d * D);
            const float u0 = x0[d], u1 = x1[d];
            #pragma unroll
            for (int q = 0; q < 4; q++) {
                float4 w = wr[q];
                a0[q*4+0]=fmaf(u0,w.x,a0[q*4+0]); a1[q*4+0]=fmaf(u1,w.x,a1[q*4+0]);
                a0[q*4+1]=fmaf(u0,w.y,a0[q*4+1]); a1[q*4+1]=fmaf(u1,w.y,a1[q*4+1]);
                a0[q*4+2]=fmaf(u0,w.z,a0[q*4+2]); a1[q*4+2]=fmaf(u1,w.z,a1[q*4+2]);
                a0[q*4+3]=fmaf(u0,w.w,a0[q*4+3]); a1[q*4+3]=fmaf(u1,w.w,a1[q*4+3]);
            }
        }
    }

    // ---- Store both rows (4x STG.128 each)
    float4* o0 = (float4*)(out + base_row * D);
    float4* o1 = (float4*)(out + (base_row + N / 2) * D);
    #pragma unroll
    for (int q = 0; q < 4; q++) {
        float4 v0, v1;
        v0.x = fmaxf(a0[q*4+0], 0.0f); v1.x = fmaxf(a1[q*4+0], 0.0f);
        v0.y = fmaxf(a0[q*4+1], 0.0f); v1.y = fmaxf(a1[q*4+1], 0.0f);
        v0.z = fmaxf(a0[q*4+2], 0.0f); v1.z = fmaxf(a1[q*4+2], 0.0f);
        v0.w = fmaxf(a0[q*4+3], 0.0f); v1.w = fmaxf(a1[q*4+3], 0.0f);
        o0[q] = v0;
        o1[q] = v1;
    }
}

extern "C" void kernel_launch(void* const* d_in, const int* in_sizes, int n_in,
                              void* d_out, int out_size) {
    const float* user_emb = (const float*)d_in[0];
    const float* item_emb = (const float*)d_in[1];
    float* out = (float*)d_out;
    const int B = in_sizes[1] / PARAMS;        // 16384
    const int blocks = B / SAMPLES_PER_CTA;    // 2048
    can_kernel<<<blocks, THREADS>>>(user_emb, item_emb, out);
}